// round 17
// baseline (speedup 1.0000x reference)
#include <cuda_runtime.h>
#include <cuda_fp16.h>
#include <cstdint>

// ---------------- problem constants ----------------
#define B_SZ   32768
#define DIN    512
#define DOUT   512
#define NLEV   10
#define NPB    128                 // histogram partial blocks (x256 rows)

// ---------------- GEMM tiling ----------------
#define BM     128
#define BN     128
#define BK     64                  // k per stage: A fp32 256B/row, B fp16 128B/row
#define NKB    (DIN / BK)          // 8 K-blocks
#define MAX_MT 266
#define NT     (DOUT / BN)         // 4 N-tiles
#define A_SZ   (BM * 256)          // 32768 B per stage (fp32)
#define B_SZ_S (BN * 128)          // 16384 B per stage (fp16)
#define STG_TOT (A_SZ + B_SZ_S)    // 49152 B
#define SMEM_BYTES (2 * STG_TOT)   // 98304

// ---------------- device scratch ----------------
__device__ int g_part[NPB][16];
// folded per-level matrices in fp16, [level][n][k]
__device__ __align__(16) __half g_M16[NLEV * DOUT * DIN];

// ---------------- PTX helpers ----------------
__device__ __forceinline__ uint32_t smem_u32(const void* p) {
    uint32_t a;
    asm("{ .reg .u64 t; cvta.to.shared.u64 t, %1; cvt.u32.u64 %0, t; }" : "=r"(a) : "l"(p));
    return a;
}
#define CP16(dst, src) \
    asm volatile("cp.async.cg.shared.global [%0], [%1], 16;" :: "r"(dst), "l"(src))
#define CP_COMMIT() asm volatile("cp.async.commit_group;" ::: "memory")
#define CP_WAIT0()  asm volatile("cp.async.wait_group 0;" ::: "memory")

#define LDSM4(r0, r1, r2, r3, addr) \
    asm volatile("ldmatrix.sync.aligned.m8n8.x4.shared.b16 {%0,%1,%2,%3}, [%4];" \
        : "=r"(r0), "=r"(r1), "=r"(r2), "=r"(r3) : "r"(addr))

__device__ __forceinline__ void mma16(float* d, const uint32_t* a, const uint32_t* b) {
    asm volatile(
        "mma.sync.aligned.m16n8k16.row.col.f32.f16.f16.f32 "
        "{%0,%1,%2,%3}, {%4,%5,%6,%7}, {%8,%9}, {%0,%1,%2,%3};"
        : "+f"(d[0]), "+f"(d[1]), "+f"(d[2]), "+f"(d[3])
        : "r"(a[0]), "r"(a[1]), "r"(a[2]), "r"(a[3]), "r"(b[0]), "r"(b[1]));
}

__device__ __forceinline__ uint32_t cvt2(float2 f) {
    __half2 h = __floats2half2_rn(f.x, f.y);
    return *reinterpret_cast<uint32_t*>(&h);
}

// B smem swizzle (128B rows, 8 x 16B units)
__device__ __forceinline__ uint32_t swzB(int row, int u) {
    return (uint32_t)row * 128u + (uint32_t)((u ^ (row & 7)) << 4);
}

// per-block int64-vs-int32 detection over first 2KB (L2-hot)
__device__ __forceinline__ int detect_is64(const void* val, int tid) {
    int bad = 0;
    if (tid < 256) bad = (((const unsigned long long*)val)[tid] >= 10ULL);
    return __syncthreads_count(bad) == 0;
}
__device__ __forceinline__ int load_val(const void* val, int b, int is64) {
    int v = is64 ? (int)((const long long*)val)[b] : ((const int*)val)[b];
    return v < 0 ? 0 : (v > 9 ? 9 : v);
}

// =================================================================
// Kernel 1 (fused, independent halves):
//   blocks 0..127   : per-chunk histogram partials (256 rows each)
//   blocks 128..383 : fold M[v] = sum_l C[v,l]*W[l] (fp16 out)
// =================================================================
__global__ void __launch_bounds__(256) k_prep(
        const void* __restrict__ val, const float* __restrict__ W,
        const float* __restrict__ gates, const float* __restrict__ attn) {
    int tid = threadIdx.x, bid = blockIdx.x;
    if (bid < NPB) {
        __shared__ int sc[NLEV];
        int is64 = detect_is64(val, tid);          // includes a __syncthreads
        if (tid < NLEV) sc[tid] = 0;
        __syncthreads();
        atomicAdd(&sc[load_val(val, bid * 256 + tid, is64)], 1);
        __syncthreads();
        if (tid < NLEV) g_part[bid][tid] = sc[tid];
    } else {
        __shared__ float sC[NLEV][NLEV];
        if (tid < NLEV) {
            int v = tid;
            float m = -1e30f;
            for (int l = 0; l < NLEV; l++) m = fmaxf(m, attn[v * NLEV + l]);
            float e[NLEV]; float ssum = 0.f;
            for (int l = 0; l < NLEV; l++) { e[l] = expf(attn[v * NLEV + l] - m); ssum += e[l]; }
            float inv = 1.f / ssum;
            float gv = 1.f / (1.f + expf(-gates[v]));
            for (int l = 0; l < NLEV; l++) {
                float gl = 1.f / (1.f + expf(-gates[l]));
                sC[v][l] = 0.3f * e[l] * inv * gl + ((l == v) ? 0.7f * gv : 0.f);
            }
        }
        __syncthreads();

        int p  = (bid - NPB) * 256 + tid;         // 0 .. 65535
        int n  = p >> 7;                          // output feature 0..511
        int k4 = p & 127;                         // float4 index along K

        float4 w[NLEV];
#pragma unroll
        for (int l = 0; l < NLEV; l++)
            w[l] = __ldg((const float4*)(W + ((size_t)l * DOUT + n) * DIN) + k4);

#pragma unroll
        for (int v = 0; v < NLEV; v++) {
            float4 a = make_float4(0.f, 0.f, 0.f, 0.f);
#pragma unroll
            for (int l = 0; l < NLEV; l++) {
                float cc = sC[v][l];
                a.x += cc * w[l].x; a.y += cc * w[l].y;
                a.z += cc * w[l].z; a.w += cc * w[l].w;
            }
            __half2 h0 = __floats2half2_rn(a.x, a.y);
            __half2 h1 = __floats2half2_rn(a.z, a.w);
            uint2 o;
            o.x = *reinterpret_cast<unsigned*>(&h0);
            o.y = *reinterpret_cast<unsigned*>(&h1);
            *(uint2*)(g_M16 + ((size_t)v * DOUT + n) * DIN + (size_t)k4 * 4) = o;
        }
    }
}

// =================================================================
// Kernel 2: GEMM with in-CTA gather.
//   Each CTA derives its 128 sorted row ids locally from g_part +
//   a windowed scan of valuations (deterministic, no atomics), then
//   runs the proven fp16 mma.sync mainloop (at the issue floor).
// =================================================================
__global__ void __launch_bounds__(256, 2) padic_gemm(
    const void* __restrict__ val, const float* __restrict__ x,
    const float* __restrict__ bias, float* __restrict__ out) {

    __shared__ int sp[NPB * NLEV];     // partials [b][l]
    __shared__ int stot[NLEV];
    __shared__ int sP[NPB + 1];        // per-chunk exclusive prefix for OUR level
    __shared__ int swtot[8], swoff[8];
    __shared__ int srow[BM];

    extern __shared__ char smem[];
    uint32_t sb = smem_u32(smem);
    int tid = threadIdx.x, lane = tid & 31, wid = tid >> 5;

    int is64 = detect_is64(val, tid);             // block-uniform; has barrier

    for (int i = tid; i < NPB * NLEV; i += 256)
        sp[i] = g_part[i / NLEV][i % NLEV];
    if (tid < BM) srow[tid] = 0;
    __syncthreads();

    if (tid < NLEV) {
        int s = 0;
        for (int b = 0; b < NPB; b++) s += sp[b * NLEV + tid];
        stot[tid] = s;
    }
    __syncthreads();

    // ---- tile map from totals ----
    int mt = blockIdx.x, ntile = blockIdx.y;
    int level = -1, tj = 0, acc = 0;
#pragma unroll
    for (int l = 0; l < NLEV; l++) {
        int c = stot[l];
        int tl = (c + BM - 1) >> 7;
        if (level < 0 && mt < acc + tl) { level = l; tj = mt - acc; }
        acc += tl;
    }
    if (level < 0) return;
    int s0  = tj * BM;                            // occurrence range start
    int cnt = stot[level] - s0; if (cnt > BM) cnt = BM;

    // ---- per-chunk exclusive prefix for this level (block scan, 128 el) ----
    {
        int cb = (tid < NPB) ? sp[tid * NLEV + level] : 0;
        int xs = cb;
#pragma unroll
        for (int o = 1; o < 32; o <<= 1) {
            int y = __shfl_up_sync(0xFFFFFFFFu, xs, o);
            if (lane >= o) xs += y;
        }
        if (lane == 31) swtot[wid] = xs;
        __syncthreads();
        if (tid == 0) { int a = 0; for (int w = 0; w < 8; w++) { swoff[w] = a; a += swtot[w]; } }
        __syncthreads();
        if (tid < NPB) sP[tid] = xs - cb + swoff[wid];
        if (tid == 0) sP[NPB] = stot[level];
        __syncthreads();
    }

    // ---- locate first chunk, then windowed gather (2048 vals / pass) ----
    int lo = 0, hi = NPB;
    while (lo + 1 < hi) { int mid = (lo + hi) >> 1; if (sP[mid] <= s0) lo = mid; else hi = mid; }
    for (int bw = lo; bw < NPB && sP[bw] < s0 + cnt; bw += 8) {
        int base0 = bw * 256 + tid * 8;           // 8 consecutive vals per thread
        int vloc[8]; int mcnt = 0;
#pragma unroll
        for (int j = 0; j < 8; j++) {
            int idx = base0 + j;
            int v = (idx < B_SZ) ? load_val(val, idx, is64) : -1;
            vloc[j] = v;
            mcnt += (v == level);
        }
        int xs = mcnt;
#pragma unroll
        for (int o = 1; o < 32; o <<= 1) {
            int y = __shfl_up_sync(0xFFFFFFFFu, xs, o);
            if (lane >= o) xs += y;
        }
        if (lane == 31) swtot[wid] = xs;
        __syncthreads();
        if (tid == 0) { int a = 0; for (int w = 0; w < 8; w++) { swoff[w] = a; a += swtot[w]; } }
        __syncthreads();
        int occ = sP[bw] + (xs - mcnt) + swoff[wid];
#pragma unroll
        for (int j = 0; j < 8; j++) {
            if (vloc[j] == level) {
                if (occ >= s0 && occ < s0 + cnt) srow[occ - s0] = base0 + j;
                occ++;
            }
        }
        __syncthreads();
    }
    __syncthreads();   // srow complete

    // ================= proven GEMM mainloop (unchanged) =================
    int wm = (wid & 3) * 32;
    int wn = (wid >> 2) * 64;

    // A: thread t -> row (t>>4)+16s (s=0..7), 16B unit u=t&15 of 256B chunk
    int uA = tid & 15, rA0 = tid >> 4;
    const char* pA[8];
#pragma unroll
    for (int s = 0; s < 8; s++)
        pA[s] = (const char*)(x + (size_t)srow[rA0 + 16 * s] * DIN) + uA * 16;
    uint32_t sA0 = (uint32_t)rA0 * 256u + (uint32_t)((uA ^ ((rA0 & 7) << 1)) << 4);
    // B: thread t -> row (t>>3)+32s (s=0..3), unit u=t&7 of 128B chunk
    int uB = tid & 7, rB0 = tid >> 3;
    const char* pB = (const char*)(g_M16 + ((size_t)level * DOUT
                     + (size_t)(ntile * BN + rB0)) * DIN) + uB * 16;
    uint32_t sB0 = (uint32_t)A_SZ + (uint32_t)rB0 * 128u
                 + (uint32_t)((uB ^ (rB0 & 7)) << 4);

    float accum[2][8][4];
#pragma unroll
    for (int mf = 0; mf < 2; mf++)
#pragma unroll
        for (int nf = 0; nf < 8; nf++)
#pragma unroll
            for (int q = 0; q < 4; q++) accum[mf][nf][q] = 0.f;

    // ---- prologue: stage 0 ----
    {
#pragma unroll
        for (int s = 0; s < 8; s++)
            CP16(sb + sA0 + s * 4096, pA[s]);
#pragma unroll
        for (int s = 0; s < 4; s++)
            CP16(sb + sB0 + s * 4096, pB + (size_t)s * 32768);
        CP_COMMIT();
    }

    // consumer lane constants
    int sub = lane >> 3, rr = lane & 7;
    int brow = wn + (sub >> 1) * 8 + rr;
    int bu   = sub & 1;
    int xorv = (lane >> 2) << 1;
    int inb  = (lane & 1) << 3;
    int au0  = (lane & 3) >> 1;
    uint32_t abase0 = (uint32_t)(wm + (lane >> 2)) * 256u;

    // ---- mainloop ----
    for (int kb = 0; kb < NKB; kb++) {
        CP_WAIT0();
        __syncthreads();

        if (kb + 1 < NKB) {
            uint32_t st = sb + ((kb + 1) & 1) * STG_TOT;
#pragma unroll
            for (int s = 0; s < 8; s++)
                CP16(st + sA0 + s * 4096, pA[s] + (kb + 1) * 256);
#pragma unroll
            for (int s = 0; s < 4; s++)
                CP16(st + sB0 + s * 4096, pB + (kb + 1) * 128 + (size_t)s * 32768);
        }
        CP_COMMIT();

        uint32_t stg = (uint32_t)((kb & 1) * STG_TOT);
        const char* As = smem + stg;
        uint32_t Bb = sb + stg + A_SZ;

#pragma unroll
        for (int g = 0; g < 4; g++) {
            int u0 = 4 * g + au0;
            uint32_t col0 = (uint32_t)(((u0      ^ xorv) << 4) + inb);
            uint32_t col2 = (uint32_t)((((u0 + 2) ^ xorv) << 4) + inb);
            uint32_t afr[2][4];
            uint32_t bfr[8][2];
#pragma unroll
            for (int mf = 0; mf < 2; mf++) {
                uint32_t rb = abase0 + (uint32_t)mf * 4096u;
                afr[mf][0] = cvt2(*(const float2*)(As + rb + col0));
                afr[mf][1] = cvt2(*(const float2*)(As + rb + 2048 + col0));
                afr[mf][2] = cvt2(*(const float2*)(As + rb + col2));
                afr[mf][3] = cvt2(*(const float2*)(As + rb + 2048 + col2));
            }
#pragma unroll
            for (int bf = 0; bf < 4; bf++) {
                int rown = brow + bf * 16;
                LDSM4(bfr[bf * 2][0], bfr[bf * 2][1], bfr[bf * 2 + 1][0], bfr[bf * 2 + 1][1],
                      Bb + swzB(rown, g * 2 + bu));
            }
#pragma unroll
            for (int mf = 0; mf < 2; mf++)
#pragma unroll
                for (int nf = 0; nf < 8; nf++)
                    mma16(accum[mf][nf], afr[mf], bfr[nf]);
        }
    }

    // ---- epilogue ----
    int colbase = ntile * BN + wn;
    float2 bb[8];
#pragma unroll
    for (int nf = 0; nf < 8; nf++)
        bb[nf] = __ldg((const float2*)(bias + colbase + nf * 8 + (lane & 3) * 2));
#pragma unroll
    for (int mf = 0; mf < 2; mf++) {
        int row0 = wm + mf * 16 + (lane >> 2);
        int row1 = row0 + 8;
        float* o0 = out + (size_t)srow[row0] * DOUT;
        float* o1 = out + (size_t)srow[row1] * DOUT;
        bool v0 = row0 < cnt, v1 = row1 < cnt;
#pragma unroll
        for (int nf = 0; nf < 8; nf++) {
            int col = colbase + nf * 8 + (lane & 3) * 2;
            if (v0) {
                float2 w0;
                w0.x = accum[mf][nf][0] + bb[nf].x;
                w0.y = accum[mf][nf][1] + bb[nf].y;
                *(float2*)(o0 + col) = w0;
            }
            if (v1) {
                float2 w1;
                w1.x = accum[mf][nf][2] + bb[nf].x;
                w1.y = accum[mf][nf][3] + bb[nf].y;
                *(float2*)(o1 + col) = w1;
            }
        }
    }
}

// =================================================================
// kernel_launch — 2 launches
// =================================================================
extern "C" void kernel_launch(void* const* d_in, const int* in_sizes, int n_in,
                              void* d_out, int out_size) {
    const float* x     = (const float*)d_in[0];
    const void*  val   = d_in[1];
    const float* W     = (const float*)d_in[2];
    const float* gates = (const float*)d_in[3];
    const float* attn  = (const float*)d_in[4];
    const float* bias  = (const float*)d_in[5];
    float*       out   = (float*)d_out;

    cudaFuncSetAttribute(padic_gemm, cudaFuncAttributeMaxDynamicSharedMemorySize, SMEM_BYTES);

    k_prep<<<NPB + 256, 256>>>(val, W, gates, attn);                 // hist || fold
    padic_gemm<<<dim3(MAX_MT, NT), 256, SMEM_BYTES>>>(val, x, bias, out);
}